// round 8
// baseline (speedup 1.0000x reference)
#include <cuda_runtime.h>
#include <cuda_fp16.h>
#include <cstdint>

#define D 128
#define BM 64
#define N_MAX 100000
#define E_MAX 3200000

// ---- packed f32x2 helpers (2x fp32 FMA throughput on sm_103a) -------------
#define FMA_F32X2(d, a, b, c) \
    asm("fma.rn.f32x2 %0, %1, %2, %3;" : "=l"(d) : "l"(a), "l"(b), "l"(c))
#define ADD_F32X2(d, a, b) \
    asm("add.rn.f32x2 %0, %1, %2;" : "=l"(d) : "l"(a), "l"(b))
#define PACK_DUP_F32X2(out, r) \
    asm("mov.b64 %0, {%1, %1};" : "=l"(out) : "r"(r))

static __device__ __forceinline__ unsigned h2_to_u32(__half2 h) {
    return *reinterpret_cast<unsigned*>(&h);
}
static __device__ __forceinline__ __half2 u32_to_h2(unsigned u) {
    return *reinterpret_cast<__half2*>(&u);
}

// Scratch
__device__ uint2  g_hh[N_MAX * 32];        // h in fp16: 4 halves per lane-slot
__device__ float4 g_wt4[D * D / 4];        // W^T
__device__ int    g_cnt[N_MAX];            // histogram -> cursor -> seg end
__device__ int    g_base[N_MAX];           // segment start per node
__device__ int    g_total;                 // bump allocator
__device__ int2   g_edge[E_MAX];           // grouped (src, w-bits) per slot

// ---------------------------------------------------------------------------
__global__ void zero_kernel(int n_nodes) {
    int i = blockIdx.x * blockDim.x + threadIdx.x;
    if (i < n_nodes) g_cnt[i] = 0;
    if (i == 0) g_total = 0;
}

__global__ void transpose_w_kernel(const float* __restrict__ W) {
    int idx = blockIdx.x * blockDim.x + threadIdx.x;
    int j = idx >> 7;
    int k = idx & (D - 1);
    ((float*)g_wt4)[k * D + j] = W[j * D + k];
}

// histogram: 4 edges per thread via int4
__global__ void hist_kernel(const int* __restrict__ dst, int n_edges) {
    int t = blockIdx.x * blockDim.x + threadIdx.x;
    int e = t * 4;
    if (e + 4 <= n_edges) {
        int4 d4 = *(const int4*)(dst + e);
        atomicAdd(&g_cnt[d4.x], 1);
        atomicAdd(&g_cnt[d4.y], 1);
        atomicAdd(&g_cnt[d4.z], 1);
        atomicAdd(&g_cnt[d4.w], 1);
    } else {
        for (int i = e; i < n_edges; i++) atomicAdd(&g_cnt[dst[i]], 1);
    }
}

__global__ void assign_base_kernel(int n_nodes) {
    __shared__ int warp_tot[8];
    __shared__ int block_base;
    int i = blockIdx.x * 256 + threadIdx.x;
    int lane = threadIdx.x & 31;
    int warp = threadIdx.x >> 5;

    int c = (i < n_nodes) ? g_cnt[i] : 0;
    int v = c;
    #pragma unroll
    for (int off = 1; off < 32; off <<= 1) {
        int t = __shfl_up_sync(0xffffffffu, v, off);
        if (lane >= off) v += t;
    }
    if (lane == 31) warp_tot[warp] = v;
    __syncthreads();
    if (warp == 0) {
        int wv = (lane < 8) ? warp_tot[lane] : 0;
        #pragma unroll
        for (int off = 1; off < 8; off <<= 1) {
            int t = __shfl_up_sync(0xffffffffu, wv, off);
            if (lane >= off) wv += t;
        }
        if (lane < 8) warp_tot[lane] = wv;
        if (lane == 7) block_base = atomicAdd(&g_total, wv);
    }
    __syncthreads();
    int excl = v - c + (warp > 0 ? warp_tot[warp - 1] : 0);
    if (i < n_nodes) {
        int base = block_base + excl;
        g_base[i] = base;
        g_cnt[i]  = base;
    }
}

// placement: 4 edges per thread via int4/float4
__global__ void place_kernel(const int* __restrict__ src,
                             const int* __restrict__ dst,
                             const float* __restrict__ w,
                             int n_edges) {
    int t = blockIdx.x * blockDim.x + threadIdx.x;
    int e = t * 4;
    if (e + 4 <= n_edges) {
        int4   s4 = *(const int4*)(src + e);
        int4   d4 = *(const int4*)(dst + e);
        float4 w4 = *(const float4*)(w + e);
        int p0 = atomicAdd(&g_cnt[d4.x], 1);
        int p1 = atomicAdd(&g_cnt[d4.y], 1);
        int p2 = atomicAdd(&g_cnt[d4.z], 1);
        int p3 = atomicAdd(&g_cnt[d4.w], 1);
        g_edge[p0] = make_int2(s4.x, __float_as_int(w4.x));
        g_edge[p1] = make_int2(s4.y, __float_as_int(w4.y));
        g_edge[p2] = make_int2(s4.z, __float_as_int(w4.z));
        g_edge[p3] = make_int2(s4.w, __float_as_int(w4.w));
    } else {
        for (int i = e; i < n_edges; i++) {
            int pos = atomicAdd(&g_cnt[dst[i]], 1);
            g_edge[pos] = make_int2(src[i], __float_as_int(w[i]));
        }
    }
}

// ---------------------------------------------------------------------------
// GEMM: h = x @ W^T + b with packed f32x2 FMA; epilogue rounds h to fp16.
// ---------------------------------------------------------------------------
__global__ __launch_bounds__(256, 2)
void gemm_kernel(const float* __restrict__ x, const float* __restrict__ bias,
                 int n_rows) {
    extern __shared__ float4 smem4[];
    float4* Ws4 = smem4;                 // [128][32] f4
    float4* Xs4 = smem4 + D * (D / 4);   // [64][32]  f4

    const int tid  = threadIdx.x;
    const int row0 = blockIdx.x * BM;
    const int rows = min(BM, n_rows - row0);

    #pragma unroll
    for (int i = 0; i < (D * D / 4) / 256; i++)
        Ws4[tid + i * 256] = g_wt4[tid + i * 256];
    {
        const float4* x4 = (const float4*)(x + (long long)row0 * D);
        const int nf4 = rows * (D / 4);
        for (int i = tid; i < nf4; i += 256)
            Xs4[i] = x4[i];
    }
    __syncthreads();

    const int warp = tid >> 5;
    const int lane = tid & 31;
    const int r0 = warp * 8;

    const ulonglong2* Ws2 = (const ulonglong2*)Ws4;

    unsigned long long acc[8][2];
    #pragma unroll
    for (int i = 0; i < 8; i++) { acc[i][0] = 0ull; acc[i][1] = 0ull; }

    #pragma unroll 4
    for (int k = 0; k < D; k += 4) {
        ulonglong2 wv0 = Ws2[(k + 0) * 32 + lane];
        ulonglong2 wv1 = Ws2[(k + 1) * 32 + lane];
        ulonglong2 wv2 = Ws2[(k + 2) * 32 + lane];
        ulonglong2 wv3 = Ws2[(k + 3) * 32 + lane];
        #pragma unroll
        for (int i = 0; i < 8; i++) {
            float4 xv = Xs4[(r0 + i) * 32 + (k >> 2)];  // warp broadcast
            unsigned long long xd;
            PACK_DUP_F32X2(xd, __float_as_uint(xv.x));
            FMA_F32X2(acc[i][0], xd, wv0.x, acc[i][0]);
            FMA_F32X2(acc[i][1], xd, wv0.y, acc[i][1]);
            PACK_DUP_F32X2(xd, __float_as_uint(xv.y));
            FMA_F32X2(acc[i][0], xd, wv1.x, acc[i][0]);
            FMA_F32X2(acc[i][1], xd, wv1.y, acc[i][1]);
            PACK_DUP_F32X2(xd, __float_as_uint(xv.z));
            FMA_F32X2(acc[i][0], xd, wv2.x, acc[i][0]);
            FMA_F32X2(acc[i][1], xd, wv2.y, acc[i][1]);
            PACK_DUP_F32X2(xd, __float_as_uint(xv.w));
            FMA_F32X2(acc[i][0], xd, wv3.x, acc[i][0]);
            FMA_F32X2(acc[i][1], xd, wv3.y, acc[i][1]);
        }
    }

    ulonglong2 bv = ((const ulonglong2*)bias)[lane];
    #pragma unroll
    for (int i = 0; i < 8; i++) {
        int r = r0 + i;
        if (r < rows) {
            ulonglong2 o;
            ADD_F32X2(o.x, acc[i][0], bv.x);
            ADD_F32X2(o.y, acc[i][1], bv.y);
            float2 p0 = *(float2*)&o.x;
            float2 p1 = *(float2*)&o.y;
            uint2 hh;
            hh.x = h2_to_u32(__floats2half2_rn(p0.x, p0.y));
            hh.y = h2_to_u32(__floats2half2_rn(p1.x, p1.y));
            g_hh[(long long)(row0 + r) * 32 + lane] = hh;
        }
    }
}

// ---------------------------------------------------------------------------
// aggregate: one warp per node, lane owns 4 columns. fp16 gather (8B/lane),
// fp32 accumulation. 8-way unroll for MLP=8.
// ---------------------------------------------------------------------------
__global__ __launch_bounds__(256)
void aggregate_kernel(float* __restrict__ out, int n_nodes) {
    int node = (blockIdx.x * 256 + threadIdx.x) >> 5;
    int lane = threadIdx.x & 31;
    if (node >= n_nodes) return;

    int beg = g_base[node];
    int end = g_cnt[node];

    float4 acc = make_float4(0.f, 0.f, 0.f, 0.f);

    int i = beg;
    for (; i + 8 <= end; i += 8) {
        int2 ed[8];
        uint2 hv[8];
        #pragma unroll
        for (int j = 0; j < 8; j++) ed[j] = g_edge[i + j];
        #pragma unroll
        for (int j = 0; j < 8; j++) hv[j] = g_hh[(long long)ed[j].x * 32 + lane];
        #pragma unroll
        for (int j = 0; j < 8; j++) {
            float wv = __int_as_float(ed[j].y);
            float2 a  = __half22float2(u32_to_h2(hv[j].x));
            float2 bq = __half22float2(u32_to_h2(hv[j].y));
            acc.x += a.x * wv; acc.y += a.y * wv;
            acc.z += bq.x * wv; acc.w += bq.y * wv;
        }
    }
    for (; i < end; i++) {
        int2 e = g_edge[i];
        float wv = __int_as_float(e.y);
        uint2 hv = g_hh[(long long)e.x * 32 + lane];
        float2 a  = __half22float2(u32_to_h2(hv.x));
        float2 bq = __half22float2(u32_to_h2(hv.y));
        acc.x += a.x * wv; acc.y += a.y * wv; acc.z += bq.x * wv; acc.w += bq.y * wv;
    }

    ((float4*)out)[(long long)node * 32 + lane] = acc;
}

// ---------------------------------------------------------------------------
extern "C" void kernel_launch(void* const* d_in, const int* in_sizes, int n_in,
                              void* d_out, int out_size) {
    const float* x   = (const float*)d_in[0];
    const float* w   = (const float*)d_in[1];
    const float* W   = (const float*)d_in[2];
    const float* b   = (const float*)d_in[3];
    const int*   src = (const int*)d_in[4];   // int32 (JAX x64 disabled)
    const int*   dst = (const int*)d_in[5];

    int N = in_sizes[0] / D;
    int E = in_sizes[1];
    float* out = (float*)d_out;

    int nb_nodes = (N + 255) / 256;
    int nb_e4    = (E / 4 + 255) / 256 + 1;   // 4 edges/thread kernels

    cudaStream_t s2;
    cudaStreamCreate(&s2);
    cudaEvent_t evFork, evJoin;
    cudaEventCreateWithFlags(&evFork, cudaEventDisableTiming);
    cudaEventCreateWithFlags(&evJoin, cudaEventDisableTiming);

    // Fork immediately: GEMM branch (transpose + gemm) on s2,
    // sort branch (zero + hist + assign + place) on stream 0.
    cudaEventRecord(evFork, 0);
    cudaStreamWaitEvent(s2, evFork, 0);

    transpose_w_kernel<<<(D * D) / 256, 256, 0, s2>>>(W);
    const int smem_bytes = (D * D + BM * D) * sizeof(float);  // 96 KB
    cudaFuncSetAttribute(gemm_kernel,
                         cudaFuncAttributeMaxDynamicSharedMemorySize, smem_bytes);
    gemm_kernel<<<(N + BM - 1) / BM, 256, smem_bytes, s2>>>(x, b, N);
    cudaEventRecord(evJoin, s2);

    zero_kernel<<<nb_nodes, 256>>>(N);
    hist_kernel<<<nb_e4, 256>>>(dst, E);
    assign_base_kernel<<<nb_nodes, 256>>>(N);
    place_kernel<<<nb_e4, 256>>>(src, dst, w, E);

    cudaStreamWaitEvent(0, evJoin, 0);

    int nb_agg = (N * 32 + 255) / 256;   // one warp per node
    aggregate_kernel<<<nb_agg, 256>>>(out, N);

    cudaStreamCaptureStatus st = cudaStreamCaptureStatusNone;
    cudaStreamIsCapturing(0, &st);
    if (st == cudaStreamCaptureStatusNone) {
        cudaStreamDestroy(s2);
        cudaEventDestroy(evFork);
        cudaEventDestroy(evJoin);
    }
}

// round 9
// speedup vs baseline: 1.0726x; 1.0726x over previous
#include <cuda_runtime.h>
#include <cuda_fp16.h>
#include <cstdint>

#define D 128
#define BM 64
#define N_MAX 100000
#define E_MAX 3200000
#define CAP 128          // bucket capacity per node (Poisson(32) -> P(>128)~1e-40)

// ---- packed f32x2 helpers --------------------------------------------------
#define FMA_F32X2(d, a, b, c) \
    asm("fma.rn.f32x2 %0, %1, %2, %3;" : "=l"(d) : "l"(a), "l"(b), "l"(c))
#define ADD_F32X2(d, a, b) \
    asm("add.rn.f32x2 %0, %1, %2;" : "=l"(d) : "l"(a), "l"(b))
#define PACK_DUP_F32X2(out, r) \
    asm("mov.b64 %0, {%1, %1};" : "=l"(out) : "r"(r))

static __device__ __forceinline__ unsigned h2_to_u32(__half2 h) {
    return *reinterpret_cast<unsigned*>(&h);
}
static __device__ __forceinline__ __half2 u32_to_h2(unsigned u) {
    return *reinterpret_cast<__half2*>(&u);
}

// Scratch
__device__ uint2  g_hh[N_MAX * 32];          // h in fp16 (4 halves / lane-slot)
__device__ float4 g_wt4[D * D / 4];          // W^T
__device__ int    g_cnt[N_MAX];              // per-node cursor
__device__ int2   g_bkt[(long long)N_MAX * CAP];  // (src, w-bits) buckets
__device__ int    g_ovf_cnt;                 // overflow edges (expected 0)
__device__ int4   g_ovf[4096];               // (src, dst, w-bits, pad)

// ---------------------------------------------------------------------------
__global__ void zero_kernel(int n_nodes) {
    int i = blockIdx.x * blockDim.x + threadIdx.x;
    if (i < n_nodes) g_cnt[i] = 0;
    if (i == 0) g_ovf_cnt = 0;
}

__global__ void transpose_w_kernel(const float* __restrict__ W) {
    int idx = blockIdx.x * blockDim.x + threadIdx.x;
    int j = idx >> 7;
    int k = idx & (D - 1);
    ((float*)g_wt4)[k * D + j] = W[j * D + k];
}

// single-pass placement into fixed-stride buckets (4 edges per thread)
__global__ void place_kernel(const int* __restrict__ src,
                             const int* __restrict__ dst,
                             const float* __restrict__ w,
                             int n_edges) {
    int t = blockIdx.x * blockDim.x + threadIdx.x;
    int e = t * 4;
    #pragma unroll
    for (int j = 0; j < 4; j++) {
        int i = e + j;
        if (i >= n_edges) return;
        int s = src[i];
        int d = dst[i];
        int wb = __float_as_int(w[i]);
        int pos = atomicAdd(&g_cnt[d], 1);
        if (pos < CAP) {
            g_bkt[(long long)d * CAP + pos] = make_int2(s, wb);
        } else {
            int o = atomicAdd(&g_ovf_cnt, 1);
            if (o < 4096) g_ovf[o] = make_int4(s, d, wb, 0);
        }
    }
}

// ---------------------------------------------------------------------------
// GEMM: h = x @ W^T + b with packed f32x2 FMA; epilogue rounds h to fp16.
// ---------------------------------------------------------------------------
__global__ __launch_bounds__(256, 2)
void gemm_kernel(const float* __restrict__ x, const float* __restrict__ bias,
                 int n_rows) {
    extern __shared__ float4 smem4[];
    float4* Ws4 = smem4;                 // [128][32] f4
    float4* Xs4 = smem4 + D * (D / 4);   // [64][32]  f4

    const int tid  = threadIdx.x;
    const int row0 = blockIdx.x * BM;
    const int rows = min(BM, n_rows - row0);

    #pragma unroll
    for (int i = 0; i < (D * D / 4) / 256; i++)
        Ws4[tid + i * 256] = g_wt4[tid + i * 256];
    {
        const float4* x4 = (const float4*)(x + (long long)row0 * D);
        const int nf4 = rows * (D / 4);
        for (int i = tid; i < nf4; i += 256)
            Xs4[i] = x4[i];
    }
    __syncthreads();

    const int warp = tid >> 5;
    const int lane = tid & 31;
    const int r0 = warp * 8;

    const ulonglong2* Ws2 = (const ulonglong2*)Ws4;

    unsigned long long acc[8][2];
    #pragma unroll
    for (int i = 0; i < 8; i++) { acc[i][0] = 0ull; acc[i][1] = 0ull; }

    #pragma unroll 4
    for (int k = 0; k < D; k += 4) {
        ulonglong2 wv0 = Ws2[(k + 0) * 32 + lane];
        ulonglong2 wv1 = Ws2[(k + 1) * 32 + lane];
        ulonglong2 wv2 = Ws2[(k + 2) * 32 + lane];
        ulonglong2 wv3 = Ws2[(k + 3) * 32 + lane];
        #pragma unroll
        for (int i = 0; i < 8; i++) {
            float4 xv = Xs4[(r0 + i) * 32 + (k >> 2)];  // warp broadcast
            unsigned long long xd;
            PACK_DUP_F32X2(xd, __float_as_uint(xv.x));
            FMA_F32X2(acc[i][0], xd, wv0.x, acc[i][0]);
            FMA_F32X2(acc[i][1], xd, wv0.y, acc[i][1]);
            PACK_DUP_F32X2(xd, __float_as_uint(xv.y));
            FMA_F32X2(acc[i][0], xd, wv1.x, acc[i][0]);
            FMA_F32X2(acc[i][1], xd, wv1.y, acc[i][1]);
            PACK_DUP_F32X2(xd, __float_as_uint(xv.z));
            FMA_F32X2(acc[i][0], xd, wv2.x, acc[i][0]);
            FMA_F32X2(acc[i][1], xd, wv2.y, acc[i][1]);
            PACK_DUP_F32X2(xd, __float_as_uint(xv.w));
            FMA_F32X2(acc[i][0], xd, wv3.x, acc[i][0]);
            FMA_F32X2(acc[i][1], xd, wv3.y, acc[i][1]);
        }
    }

    ulonglong2 bv = ((const ulonglong2*)bias)[lane];
    #pragma unroll
    for (int i = 0; i < 8; i++) {
        int r = r0 + i;
        if (r < rows) {
            ulonglong2 o;
            ADD_F32X2(o.x, acc[i][0], bv.x);
            ADD_F32X2(o.y, acc[i][1], bv.y);
            float2 p0 = *(float2*)&o.x;
            float2 p1 = *(float2*)&o.y;
            uint2 hh;
            hh.x = h2_to_u32(__floats2half2_rn(p0.x, p0.y));
            hh.y = h2_to_u32(__floats2half2_rn(p1.x, p1.y));
            g_hh[(long long)(row0 + r) * 32 + lane] = hh;
        }
    }
}

// ---------------------------------------------------------------------------
// aggregate: one warp per node over its bucket. fp16 gather, fp32 accum.
// ---------------------------------------------------------------------------
__global__ __launch_bounds__(256)
void aggregate_kernel(float* __restrict__ out, int n_nodes) {
    int node = (blockIdx.x * 256 + threadIdx.x) >> 5;
    int lane = threadIdx.x & 31;
    if (node >= n_nodes) return;

    const int2* seg = g_bkt + (long long)node * CAP;
    int cnt = g_cnt[node];
    int end = min(cnt, CAP);

    float4 acc = make_float4(0.f, 0.f, 0.f, 0.f);

    int i = 0;
    for (; i + 8 <= end; i += 8) {
        int2 ed[8];
        uint2 hv[8];
        #pragma unroll
        for (int j = 0; j < 8; j++) ed[j] = seg[i + j];
        #pragma unroll
        for (int j = 0; j < 8; j++) hv[j] = g_hh[(long long)ed[j].x * 32 + lane];
        #pragma unroll
        for (int j = 0; j < 8; j++) {
            float wv = __int_as_float(ed[j].y);
            float2 a  = __half22float2(u32_to_h2(hv[j].x));
            float2 bq = __half22float2(u32_to_h2(hv[j].y));
            acc.x += a.x * wv; acc.y += a.y * wv;
            acc.z += bq.x * wv; acc.w += bq.y * wv;
        }
    }
    for (; i < end; i++) {
        int2 e = seg[i];
        float wv = __int_as_float(e.y);
        uint2 hv = g_hh[(long long)e.x * 32 + lane];
        float2 a  = __half22float2(u32_to_h2(hv.x));
        float2 bq = __half22float2(u32_to_h2(hv.y));
        acc.x += a.x * wv; acc.y += a.y * wv; acc.z += bq.x * wv; acc.w += bq.y * wv;
    }

    ((float4*)out)[(long long)node * 32 + lane] = acc;
}

// ---------------------------------------------------------------------------
// fixup: process overflow edges (expected 0) with vector reductions.
// ---------------------------------------------------------------------------
__global__ void fixup_kernel(float* __restrict__ out) {
    int n = min(g_ovf_cnt, 4096);
    int lane = threadIdx.x & 31;
    int wid_global = (blockIdx.x * blockDim.x + threadIdx.x) >> 5;
    int nwarps = (gridDim.x * blockDim.x) >> 5;
    for (int e = wid_global; e < n; e += nwarps) {
        int4 ov = g_ovf[e];
        float wv = __int_as_float(ov.z);
        uint2 hv = g_hh[(long long)ov.x * 32 + lane];
        float2 a  = __half22float2(u32_to_h2(hv.x));
        float2 bq = __half22float2(u32_to_h2(hv.y));
        float* p = out + (long long)ov.y * D + lane * 4;
        asm volatile("red.global.add.v4.f32 [%0], {%1, %2, %3, %4};"
                     :: "l"(p), "f"(a.x * wv), "f"(a.y * wv),
                        "f"(bq.x * wv), "f"(bq.y * wv) : "memory");
    }
}

// ---------------------------------------------------------------------------
extern "C" void kernel_launch(void* const* d_in, const int* in_sizes, int n_in,
                              void* d_out, int out_size) {
    const float* x   = (const float*)d_in[0];
    const float* w   = (const float*)d_in[1];
    const float* W   = (const float*)d_in[2];
    const float* b   = (const float*)d_in[3];
    const int*   src = (const int*)d_in[4];   // int32 (JAX x64 disabled)
    const int*   dst = (const int*)d_in[5];

    int N = in_sizes[0] / D;
    int E = in_sizes[1];
    float* out = (float*)d_out;

    int nb_nodes = (N + 255) / 256;
    int nb_e4    = (E + 4 * 256 - 1) / (4 * 256);

    cudaStream_t s2;
    cudaStreamCreate(&s2);
    cudaEvent_t evFork, evJoin;
    cudaEventCreateWithFlags(&evFork, cudaEventDisableTiming);
    cudaEventCreateWithFlags(&evJoin, cudaEventDisableTiming);

    // Fork: GEMM branch on s2, bucket branch on stream 0.
    cudaEventRecord(evFork, 0);
    cudaStreamWaitEvent(s2, evFork, 0);

    transpose_w_kernel<<<(D * D) / 256, 256, 0, s2>>>(W);
    const int smem_bytes = (D * D + BM * D) * sizeof(float);  // 96 KB
    cudaFuncSetAttribute(gemm_kernel,
                         cudaFuncAttributeMaxDynamicSharedMemorySize, smem_bytes);
    gemm_kernel<<<(N + BM - 1) / BM, 256, smem_bytes, s2>>>(x, b, N);
    cudaEventRecord(evJoin, s2);

    zero_kernel<<<nb_nodes, 256>>>(N);
    place_kernel<<<nb_e4, 256>>>(src, dst, w, E);

    cudaStreamWaitEvent(0, evJoin, 0);

    int nb_agg = (N * 32 + 255) / 256;   // one warp per node
    aggregate_kernel<<<nb_agg, 256>>>(out, N);
    fixup_kernel<<<16, 256>>>(out);

    cudaStreamCaptureStatus st = cudaStreamCaptureStatusNone;
    cudaStreamIsCapturing(0, &st);
    if (st == cudaStreamCaptureStatusNone) {
        cudaStreamDestroy(s2);
        cudaEventDestroy(evFork);
        cudaEventDestroy(evJoin);
    }
}